// round 6
// baseline (speedup 1.0000x reference)
#include <cuda_runtime.h>

// out[b, t, f] = (t == (int)((1.0f - x[b,f]) * 100.0f)) ? 1.0f : 0.0f
// B=2048, T=100, F=1024. Output 839 MB -> pure HBM-store-bound.
// R6: 256-bit stores (st.global.cs.v8.f32, sm_103a-only) — halve store
//     request count for better DRAM write-burst packing. TCHUNK=5 kept.

#define B 2048
#define T 100
#define TCHUNK 5
#define NCHUNK (T / TCHUNK)   // 20
#define F 1024
#define F8 (F / 8)            // 128

__global__ __launch_bounds__(256, 8)
void spike_latency_kernel(const float* __restrict__ x, float* __restrict__ out) {
    int gtid = blockIdx.x * blockDim.x + threadIdx.x;   // 0 .. B*F8-1
    int b  = gtid >> 7;        // / F8
    int f8 = gtid & (F8 - 1);  // % F8
    int t0 = blockIdx.y * TCHUNK;

    // 256-bit load of 8 x-values
    float x0, x1, x2, x3, x4, x5, x6, x7;
    const float* px = x + (size_t)gtid * 8;
    asm volatile("ld.global.nc.v8.f32 {%0,%1,%2,%3,%4,%5,%6,%7}, [%8];"
                 : "=f"(x0), "=f"(x1), "=f"(x2), "=f"(x3),
                   "=f"(x4), "=f"(x5), "=f"(x6), "=f"(x7)
                 : "l"(px));

    int s0 = (int)((1.0f - x0) * 100.0f);
    int s1 = (int)((1.0f - x1) * 100.0f);
    int s2 = (int)((1.0f - x2) * 100.0f);
    int s3 = (int)((1.0f - x3) * 100.0f);
    int s4 = (int)((1.0f - x4) * 100.0f);
    int s5 = (int)((1.0f - x5) * 100.0f);
    int s6 = (int)((1.0f - x6) * 100.0f);
    int s7 = (int)((1.0f - x7) * 100.0f);

    float* po = out + (size_t)b * (T * F) + (size_t)t0 * F + (size_t)f8 * 8;

#pragma unroll
    for (int i = 0; i < TCHUNK; i++) {
        int t = t0 + i;
        float v0 = (t == s0) ? 1.0f : 0.0f;
        float v1 = (t == s1) ? 1.0f : 0.0f;
        float v2 = (t == s2) ? 1.0f : 0.0f;
        float v3 = (t == s3) ? 1.0f : 0.0f;
        float v4 = (t == s4) ? 1.0f : 0.0f;
        float v5 = (t == s5) ? 1.0f : 0.0f;
        float v6 = (t == s6) ? 1.0f : 0.0f;
        float v7 = (t == s7) ? 1.0f : 0.0f;
        asm volatile("st.global.cs.v8.f32 [%0], {%1,%2,%3,%4,%5,%6,%7,%8};"
                     :: "l"(po + (size_t)i * F),
                        "f"(v0), "f"(v1), "f"(v2), "f"(v3),
                        "f"(v4), "f"(v5), "f"(v6), "f"(v7)
                     : "memory");
    }
}

extern "C" void kernel_launch(void* const* d_in, const int* in_sizes, int n_in,
                              void* d_out, int out_size) {
    const float* x = (const float*)d_in[0];
    float* out = (float*)d_out;
    dim3 grid(B * F8 / 256, NCHUNK);   // (1024, 20)
    spike_latency_kernel<<<grid, 256>>>(x, out);
}

// round 7
// speedup vs baseline: 1.1470x; 1.1470x over previous
#include <cuda_runtime.h>

// out[b, t, f] = (t == (int)((1.0f - x[b,f]) * 100.0f)) ? 1.0f : 0.0f
// B=2048, T=100, F=1024. Output 839 MB -> pure HBM-store-bound.
// R7: revert to R5 float4 structure (v8 regression), swap block ordering so
//     t-chunks iterate fastest -> concurrent wave writes a dense ~24 MB
//     footprint (row/bank locality probe) + perfect L2 temporal reuse of x.

#define B 2048
#define T 100
#define TCHUNK 5
#define NCHUNK (T / TCHUNK)   // 20
#define F 1024
#define F4 (F / 4)            // 256

__global__ __launch_bounds__(256, 8)
void spike_latency_kernel(const float4* __restrict__ x, float4* __restrict__ out) {
    // t0-fastest block ordering: consecutive blocks share the same batch row.
    int bx = blockIdx.x;                 // 0 .. B*NCHUNK-1
    int b  = bx / NCHUNK;                // batch row
    int t0 = (bx % NCHUNK) * TCHUNK;     // time chunk start
    int f4 = threadIdx.x;                // 0 .. 255

    float4 xv = __ldg(x + (size_t)b * F4 + f4);
    int s0 = (int)((1.0f - xv.x) * 100.0f);
    int s1 = (int)((1.0f - xv.y) * 100.0f);
    int s2 = (int)((1.0f - xv.z) * 100.0f);
    int s3 = (int)((1.0f - xv.w) * 100.0f);

    float4* po = out + (size_t)b * (T * F4) + (size_t)t0 * F4 + f4;

#pragma unroll
    for (int i = 0; i < TCHUNK; i++) {
        int t = t0 + i;
        float4 v;
        v.x = (t == s0) ? 1.0f : 0.0f;
        v.y = (t == s1) ? 1.0f : 0.0f;
        v.z = (t == s2) ? 1.0f : 0.0f;
        v.w = (t == s3) ? 1.0f : 0.0f;
        __stcs(po + (size_t)i * F4, v);   // evict-first streaming store
    }
}

extern "C" void kernel_launch(void* const* d_in, const int* in_sizes, int n_in,
                              void* d_out, int out_size) {
    const float4* x = (const float4*)d_in[0];
    float4* out = (float4*)d_out;
    spike_latency_kernel<<<B * NCHUNK, 256>>>(x, out);   // 40960 blocks
}

// round 8
// speedup vs baseline: 1.1629x; 1.0139x over previous
#include <cuda_runtime.h>

// out[b, t, f] = (t == (int)((1.0f - x[b,f]) * 100.0f)) ? 1.0f : 0.0f
// B=2048, T=100, F=1024. Output 839 MB -> pure HBM-store-bound.
// R8: t-fastest dense ordering (R7) + TCHUNK 5 -> 2 (102400 blocks) to
//     further shrink wave-boundary drain bubbles. x reads all L2-resident.

#define B 2048
#define T 100
#define TCHUNK 2
#define NCHUNK (T / TCHUNK)   // 50
#define F 1024
#define F4 (F / 4)            // 256

__global__ __launch_bounds__(256, 8)
void spike_latency_kernel(const float4* __restrict__ x, float4* __restrict__ out) {
    // t0-fastest block ordering: consecutive blocks share the same batch row.
    int bx = blockIdx.x;                 // 0 .. B*NCHUNK-1
    int b  = bx / NCHUNK;                // batch row
    int t0 = (bx % NCHUNK) * TCHUNK;     // time chunk start
    int f4 = threadIdx.x;                // 0 .. 255

    float4 xv = __ldg(x + (size_t)b * F4 + f4);
    int s0 = (int)((1.0f - xv.x) * 100.0f);
    int s1 = (int)((1.0f - xv.y) * 100.0f);
    int s2 = (int)((1.0f - xv.z) * 100.0f);
    int s3 = (int)((1.0f - xv.w) * 100.0f);

    float4* po = out + (size_t)b * (T * F4) + (size_t)t0 * F4 + f4;

#pragma unroll
    for (int i = 0; i < TCHUNK; i++) {
        int t = t0 + i;
        float4 v;
        v.x = (t == s0) ? 1.0f : 0.0f;
        v.y = (t == s1) ? 1.0f : 0.0f;
        v.z = (t == s2) ? 1.0f : 0.0f;
        v.w = (t == s3) ? 1.0f : 0.0f;
        __stcs(po + (size_t)i * F4, v);   // evict-first streaming store
    }
}

extern "C" void kernel_launch(void* const* d_in, const int* in_sizes, int n_in,
                              void* d_out, int out_size) {
    const float4* x = (const float4*)d_in[0];
    float4* out = (float4*)d_out;
    spike_latency_kernel<<<B * NCHUNK, 256>>>(x, out);   // 102400 blocks
}